// round 4
// baseline (speedup 1.0000x reference)
#include <cuda_runtime.h>

#define DIMF 1536
#define SEQ  1560
#define LKV  4680
#define NH   12
#define HD   128

// scratch (allocation-free: device globals)
__device__ float g_q[SEQ * DIMF];
__device__ float g_k[SEQ * DIMF];
__device__ float g_v[SEQ * DIMF];
__device__ float g_o[SEQ * DIMF];

__device__ __forceinline__ unsigned f2tf(float f) {
    unsigned u; asm("cvt.rna.tf32.f32 %0,%1;" : "=r"(u) : "f"(f)); return u;
}

// D += A*B, m16n8k8 tf32, row.col
__device__ __forceinline__ void mma8(float* d, const unsigned* a, const unsigned* b) {
    asm volatile(
        "mma.sync.aligned.m16n8k8.row.col.f32.tf32.tf32.f32 "
        "{%0,%1,%2,%3},{%4,%5,%6,%7},{%8,%9},{%0,%1,%2,%3};"
        : "+f"(d[0]), "+f"(d[1]), "+f"(d[2]), "+f"(d[3])
        : "r"(a[0]), "r"(a[1]), "r"(a[2]), "r"(a[3]), "r"(b[0]), "r"(b[1]));
}

// ---------------------------------------------------------------------------
// GEMM: out[M,1536] = A[M,1536] @ W[1536,1536] + bias. tf32 mma, BM=BN=128,
// BK=16, 256 threads (8 warps 2x4), warp tile 64x32, register prefetch.
// ---------------------------------------------------------------------------
#define APAD 20
#define BPAD 136
__global__ __launch_bounds__(256) void gemm_tf32(
    const float* __restrict__ A, const float* __restrict__ W,
    const float* __restrict__ bias, float* __restrict__ out, int M)
{
    __shared__ unsigned As[128 * APAD];  // [m][k], pad 20 -> conflict-free a-frags
    __shared__ unsigned Bs[16 * BPAD];   // [k][n], pad 136 -> conflict-free b-frags
    const int bm = blockIdx.x * 128, bn = blockIdx.y * 128;
    const int tid = threadIdx.x, lane = tid & 31, warp = tid >> 5;
    const int wm = (warp >> 2) * 64, wn = (warp & 3) * 32;
    const int gi = lane >> 2, ti = lane & 3;

    float acc[4][4][4];
#pragma unroll
    for (int i = 0; i < 4; i++)
#pragma unroll
        for (int j = 0; j < 4; j++)
#pragma unroll
            for (int c = 0; c < 4; c++) acc[i][j][c] = 0.f;

    // loader index precompute: two float4 per thread for each of A,B
    const int fa0 = tid * 2, fa1 = tid * 2 + 1;

    float4 ra[2], rb[2];
    {
        int m0 = fa0 >> 2, kq0 = (fa0 & 3) * 4;
        int m1 = fa1 >> 2, kq1 = (fa1 & 3) * 4;
        ra[0] = (bm + m0 < M) ? *(const float4*)(A + (size_t)(bm + m0) * DIMF + kq0) : make_float4(0,0,0,0);
        ra[1] = (bm + m1 < M) ? *(const float4*)(A + (size_t)(bm + m1) * DIMF + kq1) : make_float4(0,0,0,0);
        int k0b = fa0 >> 5, n40 = (fa0 & 31) * 4;
        int k1b = fa1 >> 5, n41 = (fa1 & 31) * 4;
        rb[0] = *(const float4*)(W + (size_t)k0b * DIMF + bn + n40);
        rb[1] = *(const float4*)(W + (size_t)k1b * DIMF + bn + n41);
    }

    for (int k0 = 0; k0 < DIMF; k0 += 16) {
        // store staged tiles (convert to tf32)
        {
            int m0 = fa0 >> 2, kq0 = (fa0 & 3) * 4;
            int m1 = fa1 >> 2, kq1 = (fa1 & 3) * 4;
            uint4 u0 = { f2tf(ra[0].x), f2tf(ra[0].y), f2tf(ra[0].z), f2tf(ra[0].w) };
            uint4 u1 = { f2tf(ra[1].x), f2tf(ra[1].y), f2tf(ra[1].z), f2tf(ra[1].w) };
            *(uint4*)&As[m0 * APAD + kq0] = u0;
            *(uint4*)&As[m1 * APAD + kq1] = u1;
            int kb0 = fa0 >> 5, n40 = (fa0 & 31) * 4;
            int kb1 = fa1 >> 5, n41 = (fa1 & 31) * 4;
            uint4 v0 = { f2tf(rb[0].x), f2tf(rb[0].y), f2tf(rb[0].z), f2tf(rb[0].w) };
            uint4 v1 = { f2tf(rb[1].x), f2tf(rb[1].y), f2tf(rb[1].z), f2tf(rb[1].w) };
            *(uint4*)&Bs[kb0 * BPAD + n40] = v0;
            *(uint4*)&Bs[kb1 * BPAD + n41] = v1;
        }
        __syncthreads();

        // prefetch next k-tile
        if (k0 + 16 < DIMF) {
            int kn = k0 + 16;
            int m0 = fa0 >> 2, kq0 = (fa0 & 3) * 4;
            int m1 = fa1 >> 2, kq1 = (fa1 & 3) * 4;
            ra[0] = (bm + m0 < M) ? *(const float4*)(A + (size_t)(bm + m0) * DIMF + kn + kq0) : make_float4(0,0,0,0);
            ra[1] = (bm + m1 < M) ? *(const float4*)(A + (size_t)(bm + m1) * DIMF + kn + kq1) : make_float4(0,0,0,0);
            int kb0 = fa0 >> 5, n40 = (fa0 & 31) * 4;
            int kb1 = fa1 >> 5, n41 = (fa1 & 31) * 4;
            rb[0] = *(const float4*)(W + (size_t)(kn + kb0) * DIMF + bn + n40);
            rb[1] = *(const float4*)(W + (size_t)(kn + kb1) * DIMF + bn + n41);
        }

#pragma unroll
        for (int ks = 0; ks < 2; ks++) {
            const int kk = ks * 8;
            unsigned a[4][4], b[4][2];
#pragma unroll
            for (int mt = 0; mt < 4; mt++) {
                int r0 = wm + 16 * mt + gi;
                a[mt][0] = As[r0 * APAD + kk + ti];
                a[mt][1] = As[(r0 + 8) * APAD + kk + ti];
                a[mt][2] = As[r0 * APAD + kk + 4 + ti];
                a[mt][3] = As[(r0 + 8) * APAD + kk + 4 + ti];
            }
#pragma unroll
            for (int nt = 0; nt < 4; nt++) {
                int c = wn + 8 * nt + gi;
                b[nt][0] = Bs[(kk + ti) * BPAD + c];
                b[nt][1] = Bs[(kk + 4 + ti) * BPAD + c];
            }
#pragma unroll
            for (int mt = 0; mt < 4; mt++)
#pragma unroll
                for (int nt = 0; nt < 4; nt++)
                    mma8(acc[mt][nt], a[mt], b[nt]);
        }
        __syncthreads();
    }

    // epilogue + bias
#pragma unroll
    for (int mt = 0; mt < 4; mt++) {
#pragma unroll
        for (int nt = 0; nt < 4; nt++) {
            int gr0 = bm + wm + 16 * mt + gi;
            int col = bn + wn + 8 * nt + 2 * ti;
            float2 bv = *(const float2*)&bias[col];
            if (gr0 < M) {
                float2 r = { acc[mt][nt][0] + bv.x, acc[mt][nt][1] + bv.y };
                *(float2*)(out + (size_t)gr0 * DIMF + col) = r;
            }
            if (gr0 + 8 < M) {
                float2 r = { acc[mt][nt][2] + bv.x, acc[mt][nt][3] + bv.y };
                *(float2*)(out + (size_t)(gr0 + 8) * DIMF + col) = r;
            }
        }
    }
}

// ---------------------------------------------------------------------------
// RMSNorm + RoPE (unchanged from round 2, 11us)
// ---------------------------------------------------------------------------
__global__ __launch_bounds__(256) void rmsrope(
    float* __restrict__ qbuf, float* __restrict__ kbuf,
    const float* __restrict__ gq, const float* __restrict__ gk,
    const float* __restrict__ fre, const float* __restrict__ fim)
{
    const int t = blockIdx.x;
    float* row = (blockIdx.y == 0 ? qbuf : kbuf) + (size_t)t * DIMF;
    const float* g = blockIdx.y == 0 ? gq : gk;
    const int tid = threadIdx.x;

    float ss = 0.f;
#pragma unroll
    for (int u = 0; u < 6; u++) { float v = row[tid + u * 256]; ss += v * v; }
#pragma unroll
    for (int off = 16; off; off >>= 1) ss += __shfl_xor_sync(0xffffffffu, ss, off);
    __shared__ float red[8];
    if ((tid & 31) == 0) red[tid >> 5] = ss;
    __syncthreads();
    float tot = red[0] + red[1] + red[2] + red[3] + red[4] + red[5] + red[6] + red[7];
    float r = rsqrtf(tot * (1.f / 1536.f) + 1e-6f);

    const int wi = t % 52;
    const int hi = t / 52;
#pragma unroll
    for (int u = 0; u < 3; u++) {
        int p = tid + u * 256;
        int hh = p >> 6, c = p & 63;
        int d0 = hh * 128 + 2 * c;
        int frow = (c < 22) ? 3 : (c < 43) ? hi : wi;
        float cr = fre[frow * 64 + c], ci = fim[frow * 64 + c];
        float v0 = row[d0] * r * g[d0];
        float v1 = row[d0 + 1] * r * g[d0 + 1];
        row[d0]     = v0 * cr - v1 * ci;
        row[d0 + 1] = v0 * ci + v1 * cr;
    }
}

// ---------------------------------------------------------------------------
// Flash attention, tf32 tensor cores. Block = (64 queries, head), 128 threads
// (4 warps x 16 rows). Q fragments register-resident. K/V staged in padded
// smem (tf32), P staged in smem between QK and PV mma phases.
// smem: Ks[64][132] + Vs[128][68] + Ps[64][68] = 86016 B -> 2 blocks/SM.
// ---------------------------------------------------------------------------
#define KPAD 132
#define VPAD 68
#define PPAD 68
__global__ __launch_bounds__(128, 2) void attn_tf32(
    const float* __restrict__ q, const float* __restrict__ knew,
    const float* __restrict__ vnew, const float* __restrict__ ck,
    const float* __restrict__ cv, float* __restrict__ out)
{
    extern __shared__ unsigned sm[];
    unsigned* Ks = sm;                 // [kv 64][d 132]   (tf32 bits)
    unsigned* Vs = sm + 64 * KPAD;     // [d 128][kv 68]   (transposed, tf32)
    unsigned* Ps = Vs + 128 * VPAD;    // [q 64][kv 68]    (tf32)

    const int h = blockIdx.y, q0 = blockIdx.x * 64;
    const int tid = threadIdx.x, lane = tid & 31, warp = tid >> 5;
    const int gi = lane >> 2, ti = lane & 3;

    // Q fragments: warp rows 16w..16w+15, k=128 -> 16 k-tiles x 4 regs
    unsigned qf[16][4];
    {
        const float sc = 0.08838834764831845f; // 1/sqrt(128)
        int r0 = q0 + warp * 16 + gi, r1 = r0 + 8;
        const float* p0 = q + (size_t)r0 * DIMF + h * HD;
        const float* p1 = q + (size_t)r1 * DIMF + h * HD;
#pragma unroll
        for (int kt = 0; kt < 16; kt++) {
            int c = kt * 8 + ti;
            qf[kt][0] = (r0 < SEQ) ? f2tf(p0[c] * sc) : 0u;
            qf[kt][2] = (r0 < SEQ) ? f2tf(p0[c + 4] * sc) : 0u;
            qf[kt][1] = (r1 < SEQ) ? f2tf(p1[c] * sc) : 0u;
            qf[kt][3] = (r1 < SEQ) ? f2tf(p1[c + 4] * sc) : 0u;
        }
    }

    float m0v = -1e30f, m1v = -1e30f, l0 = 0.f, l1 = 0.f;
    float o[16][4];
#pragma unroll
    for (int i = 0; i < 16; i++)
#pragma unroll
        for (int c = 0; c < 4; c++) o[i][c] = 0.f;

    const int r = tid & 63, half = tid >> 6;

    for (int kv0 = 0; kv0 < LKV; kv0 += 64) {
        // --- stage K (row-major) and V (transposed) tiles, tf32 ---
        {
            int j = kv0 + r;
            bool ok = j < LKV;
            const float* ksrc; const float* vsrc;
            if (j < 1560)      { ksrc = ck + ((size_t)j * NH + h) * HD;
                                 vsrc = cv + ((size_t)j * NH + h) * HD; }
            else if (j < 3120) { ksrc = ck + ((size_t)(j + 1560) * NH + h) * HD;
                                 vsrc = cv + ((size_t)(j + 1560) * NH + h) * HD; }
            else               { ksrc = knew + (size_t)(j - 3120) * DIMF + h * HD;
                                 vsrc = vnew + (size_t)(j - 3120) * DIMF + h * HD; }
#pragma unroll
            for (int u = 0; u < 16; u++) {
                int d = half * 64 + u * 4;
                float4 k4 = ok ? *(const float4*)(ksrc + d) : make_float4(0,0,0,0);
                uint4 ku = { f2tf(k4.x), f2tf(k4.y), f2tf(k4.z), f2tf(k4.w) };
                *(uint4*)&Ks[r * KPAD + d] = ku;
                float4 v4 = ok ? *(const float4*)(vsrc + d) : make_float4(0,0,0,0);
                Vs[(d + 0) * VPAD + r] = f2tf(v4.x);
                Vs[(d + 1) * VPAD + r] = f2tf(v4.y);
                Vs[(d + 2) * VPAD + r] = f2tf(v4.z);
                Vs[(d + 3) * VPAD + r] = f2tf(v4.w);
            }
        }
        __syncthreads();

        // --- S = Q K^T : warp computes 16 x 64 ---
        float s[8][4];
#pragma unroll
        for (int nt = 0; nt < 8; nt++)
#pragma unroll
            for (int c = 0; c < 4; c++) s[nt][c] = 0.f;
#pragma unroll
        for (int kt = 0; kt < 16; kt++) {
#pragma unroll
            for (int nt = 0; nt < 8; nt++) {
                unsigned b[2];
                b[0] = Ks[(8 * nt + gi) * KPAD + 8 * kt + ti];
                b[1] = Ks[(8 * nt + gi) * KPAD + 8 * kt + 4 + ti];
                mma8(s[nt], qf[kt], b);
            }
        }

        // tail mask
        if (kv0 + 64 > LKV) {
#pragma unroll
            for (int nt = 0; nt < 8; nt++) {
                int col = kv0 + 8 * nt + 2 * ti;
                if (col >= LKV)     { s[nt][0] = -1e30f; s[nt][2] = -1e30f; }
                if (col + 1 >= LKV) { s[nt][1] = -1e30f; s[nt][3] = -1e30f; }
            }
        }

        // --- online softmax: slot0 = row gi, slot1 = row gi+8 ---
        const int pr = warp * 16 + gi;
        {
            float mx = -1e30f;
#pragma unroll
            for (int nt = 0; nt < 8; nt++) mx = fmaxf(mx, fmaxf(s[nt][0], s[nt][1]));
            mx = fmaxf(mx, __shfl_xor_sync(0xffffffffu, mx, 1));
            mx = fmaxf(mx, __shfl_xor_sync(0xffffffffu, mx, 2));
            float mn = fmaxf(m0v, mx);
            float al = __expf(m0v - mn);
            float rs = 0.f;
#pragma unroll
            for (int nt = 0; nt < 8; nt++) {
                float p0 = __expf(s[nt][0] - mn), p1 = __expf(s[nt][1] - mn);
                rs += p0 + p1;
                uint2 pu = { f2tf(p0), f2tf(p1) };
                *(uint2*)&Ps[pr * PPAD + 8 * nt + 2 * ti] = pu;
            }
            rs += __shfl_xor_sync(0xffffffffu, rs, 1);
            rs += __shfl_xor_sync(0xffffffffu, rs, 2);
            l0 = l0 * al + rs; m0v = mn;
#pragma unroll
            for (int nt = 0; nt < 16; nt++) { o[nt][0] *= al; o[nt][1] *= al; }
        }
        {
            float mx = -1e30f;
#pragma unroll
            for (int nt = 0; nt < 8; nt++) mx = fmaxf(mx, fmaxf(s[nt][2], s[nt][3]));
            mx = fmaxf(mx, __shfl_xor_sync(0xffffffffu, mx, 1));
            mx = fmaxf(mx, __shfl_xor_sync(0xffffffffu, mx, 2));
            float mn = fmaxf(m1v, mx);
            float al = __expf(m1v - mn);
            float rs = 0.f;
#pragma unroll
            for (int nt = 0; nt < 8; nt++) {
                float p0 = __expf(s[nt][2] - mn), p1 = __expf(s[nt][3] - mn);
                rs += p0 + p1;
                uint2 pu = { f2tf(p0), f2tf(p1) };
                *(uint2*)&Ps[(pr + 8) * PPAD + 8 * nt + 2 * ti] = pu;
            }
            rs += __shfl_xor_sync(0xffffffffu, rs, 1);
            rs += __shfl_xor_sync(0xffffffffu, rs, 2);
            l1 = l1 * al + rs; m1v = mn;
#pragma unroll
            for (int nt = 0; nt < 16; nt++) { o[nt][2] *= al; o[nt][3] *= al; }
        }
        __syncwarp();   // P written/read within the same warp only

        // --- O += P V : warp's 16 rows x 128 d ---
#pragma unroll
        for (int kt = 0; kt < 8; kt++) {
            unsigned a[4];
            a[0] = Ps[pr * PPAD + 8 * kt + ti];
            a[1] = Ps[(pr + 8) * PPAD + 8 * kt + ti];
            a[2] = Ps[pr * PPAD + 8 * kt + 4 + ti];
            a[3] = Ps[(pr + 8) * PPAD + 8 * kt + 4 + ti];
#pragma unroll
            for (int nt = 0; nt < 16; nt++) {
                unsigned b[2];
                b[0] = Vs[(8 * nt + gi) * VPAD + 8 * kt + ti];
                b[1] = Vs[(8 * nt + gi) * VPAD + 8 * kt + 4 + ti];
                mma8(o[nt], a, b);
            }
        }
        __syncthreads();
    }

    // epilogue
    {
        int r0 = q0 + warp * 16 + gi, r1 = r0 + 8;
        float i0 = 1.f / l0, i1 = 1.f / l1;
#pragma unroll
        for (int nt = 0; nt < 16; nt++) {
            int c = h * HD + 8 * nt + 2 * ti;
            if (r0 < SEQ) {
                float2 v = { o[nt][0] * i0, o[nt][1] * i0 };
                *(float2*)(out + (size_t)r0 * DIMF + c) = v;
            }
            if (r1 < SEQ) {
                float2 v = { o[nt][2] * i1, o[nt][3] * i1 };
                *(float2*)(out + (size_t)r1 * DIMF + c) = v;
            }
        }
    }
}

// ---------------------------------------------------------------------------
extern "C" void kernel_launch(void* const* d_in, const int* in_sizes, int n_in,
                              void* d_out, int out_size)
{
    (void)in_sizes; (void)n_in; (void)out_size;
    const float* x   = (const float*)d_in[0];
    const float* ck  = (const float*)d_in[1];
    const float* cv  = (const float*)d_in[2];
    const float* fre = (const float*)d_in[3];
    const float* fim = (const float*)d_in[4];
    const float* wq  = (const float*)d_in[5];
    const float* bq  = (const float*)d_in[6];
    const float* wk  = (const float*)d_in[7];
    const float* bk  = (const float*)d_in[8];
    const float* wv  = (const float*)d_in[9];
    const float* bv  = (const float*)d_in[10];
    const float* wo  = (const float*)d_in[11];
    const float* bo  = (const float*)d_in[12];
    const float* gq  = (const float*)d_in[13];
    const float* gk  = (const float*)d_in[14];
    float* out = (float*)d_out;

    float *q, *k, *v, *o;
    cudaGetSymbolAddress((void**)&q, g_q);
    cudaGetSymbolAddress((void**)&k, g_k);
    cudaGetSymbolAddress((void**)&v, g_v);
    cudaGetSymbolAddress((void**)&o, g_o);

    const int attn_smem = (64 * KPAD + 128 * VPAD + 64 * PPAD) * 4; // 86016
    cudaFuncSetAttribute(attn_tf32, cudaFuncAttributeMaxDynamicSharedMemorySize, attn_smem);

    dim3 gg(13, 12);
    gemm_tf32<<<gg, 256>>>(x, wq, bq, q, SEQ);
    gemm_tf32<<<gg, 256>>>(x, wk, bk, k, SEQ);
    gemm_tf32<<<gg, 256>>>(x, wv, bv, v, SEQ);
    rmsrope<<<dim3(SEQ, 2), 256>>>(q, k, gq, gk, fre, fim);
    attn_tf32<<<dim3(25, NH), 128, attn_smem>>>(q, k, v, ck, cv, o);
    gemm_tf32<<<gg, 256>>>(o, wo, bo, out, SEQ);
}

// round 5
// speedup vs baseline: 1.0025x; 1.0025x over previous
#include <cuda_runtime.h>

#define DIMF 1536
#define SEQ  1560
#define LKV  4680
#define NH   12
#define HD   128

// scratch (allocation-free: device globals)
__device__ float g_q[SEQ * DIMF];
__device__ float g_k[SEQ * DIMF];
__device__ float g_v[SEQ * DIMF];
__device__ float g_o[SEQ * DIMF];

__device__ __forceinline__ unsigned f2tf(float f) {
    unsigned u; asm("cvt.rna.tf32.f32 %0,%1;" : "=r"(u) : "f"(f)); return u;
}

// D += A*B, m16n8k8 tf32, row.col
__device__ __forceinline__ void mma8(float* d, const unsigned* a, const unsigned* b) {
    asm volatile(
        "mma.sync.aligned.m16n8k8.row.col.f32.tf32.tf32.f32 "
        "{%0,%1,%2,%3},{%4,%5,%6,%7},{%8,%9},{%0,%1,%2,%3};"
        : "+f"(d[0]), "+f"(d[1]), "+f"(d[2]), "+f"(d[3])
        : "r"(a[0]), "r"(a[1]), "r"(a[2]), "r"(a[3]), "r"(b[0]), "r"(b[1]));
}

// ---------------------------------------------------------------------------
// GEMM: out[M,1536] = A[M,1536] @ W[1536,1536] + bias. tf32 mma, BM=BN=128,
// BK=16, 256 threads (8 warps 2x4), warp tile 64x32, register prefetch.
// ---------------------------------------------------------------------------
#define APAD 20
#define BPAD 136
__global__ __launch_bounds__(256) void gemm_tf32(
    const float* __restrict__ A, const float* __restrict__ W,
    const float* __restrict__ bias, float* __restrict__ out, int M)
{
    __shared__ unsigned As[128 * APAD];  // [m][k], pad 20 -> conflict-free a-frags
    __shared__ unsigned Bs[16 * BPAD];   // [k][n], pad 136 -> conflict-free b-frags
    const int bm = blockIdx.x * 128, bn = blockIdx.y * 128;
    const int tid = threadIdx.x, lane = tid & 31, warp = tid >> 5;
    const int wm = (warp >> 2) * 64, wn = (warp & 3) * 32;
    const int gi = lane >> 2, ti = lane & 3;

    float acc[4][4][4];
#pragma unroll
    for (int i = 0; i < 4; i++)
#pragma unroll
        for (int j = 0; j < 4; j++)
#pragma unroll
            for (int c = 0; c < 4; c++) acc[i][j][c] = 0.f;

    // loader index precompute: two float4 per thread for each of A,B
    const int fa0 = tid * 2, fa1 = tid * 2 + 1;

    float4 ra[2], rb[2];
    {
        int m0 = fa0 >> 2, kq0 = (fa0 & 3) * 4;
        int m1 = fa1 >> 2, kq1 = (fa1 & 3) * 4;
        ra[0] = (bm + m0 < M) ? *(const float4*)(A + (size_t)(bm + m0) * DIMF + kq0) : make_float4(0,0,0,0);
        ra[1] = (bm + m1 < M) ? *(const float4*)(A + (size_t)(bm + m1) * DIMF + kq1) : make_float4(0,0,0,0);
        int k0b = fa0 >> 5, n40 = (fa0 & 31) * 4;
        int k1b = fa1 >> 5, n41 = (fa1 & 31) * 4;
        rb[0] = *(const float4*)(W + (size_t)k0b * DIMF + bn + n40);
        rb[1] = *(const float4*)(W + (size_t)k1b * DIMF + bn + n41);
    }

    for (int k0 = 0; k0 < DIMF; k0 += 16) {
        // store staged tiles (convert to tf32)
        {
            int m0 = fa0 >> 2, kq0 = (fa0 & 3) * 4;
            int m1 = fa1 >> 2, kq1 = (fa1 & 3) * 4;
            uint4 u0 = { f2tf(ra[0].x), f2tf(ra[0].y), f2tf(ra[0].z), f2tf(ra[0].w) };
            uint4 u1 = { f2tf(ra[1].x), f2tf(ra[1].y), f2tf(ra[1].z), f2tf(ra[1].w) };
            *(uint4*)&As[m0 * APAD + kq0] = u0;
            *(uint4*)&As[m1 * APAD + kq1] = u1;
            int kb0 = fa0 >> 5, n40 = (fa0 & 31) * 4;
            int kb1 = fa1 >> 5, n41 = (fa1 & 31) * 4;
            uint4 v0 = { f2tf(rb[0].x), f2tf(rb[0].y), f2tf(rb[0].z), f2tf(rb[0].w) };
            uint4 v1 = { f2tf(rb[1].x), f2tf(rb[1].y), f2tf(rb[1].z), f2tf(rb[1].w) };
            *(uint4*)&Bs[kb0 * BPAD + n40] = v0;
            *(uint4*)&Bs[kb1 * BPAD + n41] = v1;
        }
        __syncthreads();

        // prefetch next k-tile
        if (k0 + 16 < DIMF) {
            int kn = k0 + 16;
            int m0 = fa0 >> 2, kq0 = (fa0 & 3) * 4;
            int m1 = fa1 >> 2, kq1 = (fa1 & 3) * 4;
            ra[0] = (bm + m0 < M) ? *(const float4*)(A + (size_t)(bm + m0) * DIMF + kn + kq0) : make_float4(0,0,0,0);
            ra[1] = (bm + m1 < M) ? *(const float4*)(A + (size_t)(bm + m1) * DIMF + kn + kq1) : make_float4(0,0,0,0);
            int kb0 = fa0 >> 5, n40 = (fa0 & 31) * 4;
            int kb1 = fa1 >> 5, n41 = (fa1 & 31) * 4;
            rb[0] = *(const float4*)(W + (size_t)(kn + kb0) * DIMF + bn + n40);
            rb[1] = *(const float4*)(W + (size_t)(kn + kb1) * DIMF + bn + n41);
        }

#pragma unroll
        for (int ks = 0; ks < 2; ks++) {
            const int kk = ks * 8;
            unsigned a[4][4], b[4][2];
#pragma unroll
            for (int mt = 0; mt < 4; mt++) {
                int r0 = wm + 16 * mt + gi;
                a[mt][0] = As[r0 * APAD + kk + ti];
                a[mt][1] = As[(r0 + 8) * APAD + kk + ti];
                a[mt][2] = As[r0 * APAD + kk + 4 + ti];
                a[mt][3] = As[(r0 + 8) * APAD + kk + 4 + ti];
            }
#pragma unroll
            for (int nt = 0; nt < 4; nt++) {
                int c = wn + 8 * nt + gi;
                b[nt][0] = Bs[(kk + ti) * BPAD + c];
                b[nt][1] = Bs[(kk + 4 + ti) * BPAD + c];
            }
#pragma unroll
            for (int mt = 0; mt < 4; mt++)
#pragma unroll
                for (int nt = 0; nt < 4; nt++)
                    mma8(acc[mt][nt], a[mt], b[nt]);
        }
        __syncthreads();
    }

    // epilogue + bias
#pragma unroll
    for (int mt = 0; mt < 4; mt++) {
#pragma unroll
        for (int nt = 0; nt < 4; nt++) {
            int gr0 = bm + wm + 16 * mt + gi;
            int col = bn + wn + 8 * nt + 2 * ti;
            float2 bv = *(const float2*)&bias[col];
            if (gr0 < M) {
                float2 r = { acc[mt][nt][0] + bv.x, acc[mt][nt][1] + bv.y };
                *(float2*)(out + (size_t)gr0 * DIMF + col) = r;
            }
            if (gr0 + 8 < M) {
                float2 r = { acc[mt][nt][2] + bv.x, acc[mt][nt][3] + bv.y };
                *(float2*)(out + (size_t)(gr0 + 8) * DIMF + col) = r;
            }
        }
    }
}

// ---------------------------------------------------------------------------
// RMSNorm + RoPE (unchanged from round 2, 11us)
// ---------------------------------------------------------------------------
__global__ __launch_bounds__(256) void rmsrope(
    float* __restrict__ qbuf, float* __restrict__ kbuf,
    const float* __restrict__ gq, const float* __restrict__ gk,
    const float* __restrict__ fre, const float* __restrict__ fim)
{
    const int t = blockIdx.x;
    float* row = (blockIdx.y == 0 ? qbuf : kbuf) + (size_t)t * DIMF;
    const float* g = blockIdx.y == 0 ? gq : gk;
    const int tid = threadIdx.x;

    float ss = 0.f;
#pragma unroll
    for (int u = 0; u < 6; u++) { float v = row[tid + u * 256]; ss += v * v; }
#pragma unroll
    for (int off = 16; off; off >>= 1) ss += __shfl_xor_sync(0xffffffffu, ss, off);
    __shared__ float red[8];
    if ((tid & 31) == 0) red[tid >> 5] = ss;
    __syncthreads();
    float tot = red[0] + red[1] + red[2] + red[3] + red[4] + red[5] + red[6] + red[7];
    float r = rsqrtf(tot * (1.f / 1536.f) + 1e-6f);

    const int wi = t % 52;
    const int hi = t / 52;
#pragma unroll
    for (int u = 0; u < 3; u++) {
        int p = tid + u * 256;
        int hh = p >> 6, c = p & 63;
        int d0 = hh * 128 + 2 * c;
        int frow = (c < 22) ? 3 : (c < 43) ? hi : wi;
        float cr = fre[frow * 64 + c], ci = fim[frow * 64 + c];
        float v0 = row[d0] * r * g[d0];
        float v1 = row[d0 + 1] * r * g[d0 + 1];
        row[d0]     = v0 * cr - v1 * ci;
        row[d0 + 1] = v0 * ci + v1 * cr;
    }
}

// ---------------------------------------------------------------------------
// Flash attention, tf32 tensor cores. Block = (64 queries, head), 128 threads
// (4 warps x 16 rows). Q fragments register-resident. K/V staged in padded
// smem (tf32), P staged in smem between QK and PV mma phases.
// smem: Ks[64][132] + Vs[128][68] + Ps[64][68] = 86016 B -> 2 blocks/SM.
// ---------------------------------------------------------------------------
#define KPAD 132
#define VPAD 68
#define PPAD 68
__global__ __launch_bounds__(128, 2) void attn_tf32(
    const float* __restrict__ q, const float* __restrict__ knew,
    const float* __restrict__ vnew, const float* __restrict__ ck,
    const float* __restrict__ cv, float* __restrict__ out)
{
    extern __shared__ unsigned sm[];
    unsigned* Ks = sm;                 // [kv 64][d 132]   (tf32 bits)
    unsigned* Vs = sm + 64 * KPAD;     // [d 128][kv 68]   (transposed, tf32)
    unsigned* Ps = Vs + 128 * VPAD;    // [q 64][kv 68]    (tf32)

    const int h = blockIdx.y, q0 = blockIdx.x * 64;
    const int tid = threadIdx.x, lane = tid & 31, warp = tid >> 5;
    const int gi = lane >> 2, ti = lane & 3;

    // Q fragments: warp rows 16w..16w+15, k=128 -> 16 k-tiles x 4 regs
    unsigned qf[16][4];
    {
        const float sc = 0.08838834764831845f; // 1/sqrt(128)
        int r0 = q0 + warp * 16 + gi, r1 = r0 + 8;
        const float* p0 = q + (size_t)r0 * DIMF + h * HD;
        const float* p1 = q + (size_t)r1 * DIMF + h * HD;
#pragma unroll
        for (int kt = 0; kt < 16; kt++) {
            int c = kt * 8 + ti;
            qf[kt][0] = (r0 < SEQ) ? f2tf(p0[c] * sc) : 0u;
            qf[kt][2] = (r0 < SEQ) ? f2tf(p0[c + 4] * sc) : 0u;
            qf[kt][1] = (r1 < SEQ) ? f2tf(p1[c] * sc) : 0u;
            qf[kt][3] = (r1 < SEQ) ? f2tf(p1[c + 4] * sc) : 0u;
        }
    }

    float m0v = -1e30f, m1v = -1e30f, l0 = 0.f, l1 = 0.f;
    float o[16][4];
#pragma unroll
    for (int i = 0; i < 16; i++)
#pragma unroll
        for (int c = 0; c < 4; c++) o[i][c] = 0.f;

    const int r = tid & 63, half = tid >> 6;

    for (int kv0 = 0; kv0 < LKV; kv0 += 64) {
        // --- stage K (row-major) and V (transposed) tiles, tf32 ---
        {
            int j = kv0 + r;
            bool ok = j < LKV;
            const float* ksrc; const float* vsrc;
            if (j < 1560)      { ksrc = ck + ((size_t)j * NH + h) * HD;
                                 vsrc = cv + ((size_t)j * NH + h) * HD; }
            else if (j < 3120) { ksrc = ck + ((size_t)(j + 1560) * NH + h) * HD;
                                 vsrc = cv + ((size_t)(j + 1560) * NH + h) * HD; }
            else               { ksrc = knew + (size_t)(j - 3120) * DIMF + h * HD;
                                 vsrc = vnew + (size_t)(j - 3120) * DIMF + h * HD; }
#pragma unroll
            for (int u = 0; u < 16; u++) {
                int d = half * 64 + u * 4;
                float4 k4 = ok ? *(const float4*)(ksrc + d) : make_float4(0,0,0,0);
                uint4 ku = { f2tf(k4.x), f2tf(k4.y), f2tf(k4.z), f2tf(k4.w) };
                *(uint4*)&Ks[r * KPAD + d] = ku;
                float4 v4 = ok ? *(const float4*)(vsrc + d) : make_float4(0,0,0,0);
                Vs[(d + 0) * VPAD + r] = f2tf(v4.x);
                Vs[(d + 1) * VPAD + r] = f2tf(v4.y);
                Vs[(d + 2) * VPAD + r] = f2tf(v4.z);
                Vs[(d + 3) * VPAD + r] = f2tf(v4.w);
            }
        }
        __syncthreads();

        // --- S = Q K^T : warp computes 16 x 64 ---
        float s[8][4];
#pragma unroll
        for (int nt = 0; nt < 8; nt++)
#pragma unroll
            for (int c = 0; c < 4; c++) s[nt][c] = 0.f;
#pragma unroll
        for (int kt = 0; kt < 16; kt++) {
#pragma unroll
            for (int nt = 0; nt < 8; nt++) {
                unsigned b[2];
                b[0] = Ks[(8 * nt + gi) * KPAD + 8 * kt + ti];
                b[1] = Ks[(8 * nt + gi) * KPAD + 8 * kt + 4 + ti];
                mma8(s[nt], qf[kt], b);
            }
        }

        // tail mask
        if (kv0 + 64 > LKV) {
#pragma unroll
            for (int nt = 0; nt < 8; nt++) {
                int col = kv0 + 8 * nt + 2 * ti;
                if (col >= LKV)     { s[nt][0] = -1e30f; s[nt][2] = -1e30f; }
                if (col + 1 >= LKV) { s[nt][1] = -1e30f; s[nt][3] = -1e30f; }
            }
        }

        // --- online softmax: slot0 = row gi, slot1 = row gi+8 ---
        const int pr = warp * 16 + gi;
        {
            float mx = -1e30f;
#pragma unroll
            for (int nt = 0; nt < 8; nt++) mx = fmaxf(mx, fmaxf(s[nt][0], s[nt][1]));
            mx = fmaxf(mx, __shfl_xor_sync(0xffffffffu, mx, 1));
            mx = fmaxf(mx, __shfl_xor_sync(0xffffffffu, mx, 2));
            float mn = fmaxf(m0v, mx);
            float al = __expf(m0v - mn);
            float rs = 0.f;
#pragma unroll
            for (int nt = 0; nt < 8; nt++) {
                float p0 = __expf(s[nt][0] - mn), p1 = __expf(s[nt][1] - mn);
                rs += p0 + p1;
                uint2 pu = { f2tf(p0), f2tf(p1) };
                *(uint2*)&Ps[pr * PPAD + 8 * nt + 2 * ti] = pu;
            }
            rs += __shfl_xor_sync(0xffffffffu, rs, 1);
            rs += __shfl_xor_sync(0xffffffffu, rs, 2);
            l0 = l0 * al + rs; m0v = mn;
#pragma unroll
            for (int nt = 0; nt < 16; nt++) { o[nt][0] *= al; o[nt][1] *= al; }
        }
        {
            float mx = -1e30f;
#pragma unroll
            for (int nt = 0; nt < 8; nt++) mx = fmaxf(mx, fmaxf(s[nt][2], s[nt][3]));
            mx = fmaxf(mx, __shfl_xor_sync(0xffffffffu, mx, 1));
            mx = fmaxf(mx, __shfl_xor_sync(0xffffffffu, mx, 2));
            float mn = fmaxf(m1v, mx);
            float al = __expf(m1v - mn);
            float rs = 0.f;
#pragma unroll
            for (int nt = 0; nt < 8; nt++) {
                float p0 = __expf(s[nt][2] - mn), p1 = __expf(s[nt][3] - mn);
                rs += p0 + p1;
                uint2 pu = { f2tf(p0), f2tf(p1) };
                *(uint2*)&Ps[(pr + 8) * PPAD + 8 * nt + 2 * ti] = pu;
            }
            rs += __shfl_xor_sync(0xffffffffu, rs, 1);
            rs += __shfl_xor_sync(0xffffffffu, rs, 2);
            l1 = l1 * al + rs; m1v = mn;
#pragma unroll
            for (int nt = 0; nt < 16; nt++) { o[nt][2] *= al; o[nt][3] *= al; }
        }
        __syncwarp();   // P written/read within the same warp only

        // --- O += P V : warp's 16 rows x 128 d ---
#pragma unroll
        for (int kt = 0; kt < 8; kt++) {
            unsigned a[4];
            a[0] = Ps[pr * PPAD + 8 * kt + ti];
            a[1] = Ps[(pr + 8) * PPAD + 8 * kt + ti];
            a[2] = Ps[pr * PPAD + 8 * kt + 4 + ti];
            a[3] = Ps[(pr + 8) * PPAD + 8 * kt + 4 + ti];
#pragma unroll
            for (int nt = 0; nt < 16; nt++) {
                unsigned b[2];
                b[0] = Vs[(8 * nt + gi) * VPAD + 8 * kt + ti];
                b[1] = Vs[(8 * nt + gi) * VPAD + 8 * kt + 4 + ti];
                mma8(o[nt], a, b);
            }
        }
        __syncthreads();
    }

    // epilogue
    {
        int r0 = q0 + warp * 16 + gi, r1 = r0 + 8;
        float i0 = 1.f / l0, i1 = 1.f / l1;
#pragma unroll
        for (int nt = 0; nt < 16; nt++) {
            int c = h * HD + 8 * nt + 2 * ti;
            if (r0 < SEQ) {
                float2 v = { o[nt][0] * i0, o[nt][1] * i0 };
                *(float2*)(out + (size_t)r0 * DIMF + c) = v;
            }
            if (r1 < SEQ) {
                float2 v = { o[nt][2] * i1, o[nt][3] * i1 };
                *(float2*)(out + (size_t)r1 * DIMF + c) = v;
            }
        }
    }
}

// ---------------------------------------------------------------------------
extern "C" void kernel_launch(void* const* d_in, const int* in_sizes, int n_in,
                              void* d_out, int out_size)
{
    (void)in_sizes; (void)n_in; (void)out_size;
    const float* x   = (const float*)d_in[0];
    const float* ck  = (const float*)d_in[1];
    const float* cv  = (const float*)d_in[2];
    const float* fre = (const float*)d_in[3];
    const float* fim = (const float*)d_in[4];
    const float* wq  = (const float*)d_in[5];
    const float* bq  = (const float*)d_in[6];
    const float* wk  = (const float*)d_in[7];
    const float* bk  = (const float*)d_in[8];
    const float* wv  = (const float*)d_in[9];
    const float* bv  = (const float*)d_in[10];
    const float* wo  = (const float*)d_in[11];
    const float* bo  = (const float*)d_in[12];
    const float* gq  = (const float*)d_in[13];
    const float* gk  = (const float*)d_in[14];
    float* out = (float*)d_out;

    float *q, *k, *v, *o;
    cudaGetSymbolAddress((void**)&q, g_q);
    cudaGetSymbolAddress((void**)&k, g_k);
    cudaGetSymbolAddress((void**)&v, g_v);
    cudaGetSymbolAddress((void**)&o, g_o);

    const int attn_smem = (64 * KPAD + 128 * VPAD + 64 * PPAD) * 4; // 86016
    cudaFuncSetAttribute(attn_tf32, cudaFuncAttributeMaxDynamicSharedMemorySize, attn_smem);

    dim3 gg(13, 12);
    gemm_tf32<<<gg, 256>>>(x, wq, bq, q, SEQ);
    gemm_tf32<<<gg, 256>>>(x, wk, bk, k, SEQ);
    gemm_tf32<<<gg, 256>>>(x, wv, bv, v, SEQ);
    rmsrope<<<dim3(SEQ, 2), 256>>>(q, k, gq, gk, fre, fim);
    attn_tf32<<<dim3(25, NH), 128, attn_smem>>>(q, k, v, ck, cv, o);
    gemm_tf32<<<gg, 256>>>(o, wo, bo, out, SEQ);
}

// round 6
// speedup vs baseline: 1.4827x; 1.4791x over previous
#include <cuda_runtime.h>
#include <cuda_fp16.h>

#define DIMF 1536
#define SEQ  1560
#define LKV  4680
#define NH   12
#define HD   128

// scratch (allocation-free: device globals)
__device__ float g_q[SEQ * DIMF];
__device__ float g_k[SEQ * DIMF];
__device__ float g_v[SEQ * DIMF];
__device__ float g_o[SEQ * DIMF];

__device__ __forceinline__ unsigned h2u(__half2 h) {
    return *reinterpret_cast<unsigned*>(&h);
}
__device__ __forceinline__ unsigned pk2(float a, float b) {
    return h2u(__floats2half2_rn(a, b));
}

// D += A*B  (m16n8k16 fp16 inputs, fp32 accum, row.col)
__device__ __forceinline__ void mma16(float* d, const unsigned* a, const unsigned* b) {
    asm volatile(
        "mma.sync.aligned.m16n8k16.row.col.f32.f16.f16.f32 "
        "{%0,%1,%2,%3},{%4,%5,%6,%7},{%8,%9},{%0,%1,%2,%3};"
        : "+f"(d[0]), "+f"(d[1]), "+f"(d[2]), "+f"(d[3])
        : "r"(a[0]), "r"(a[1]), "r"(a[2]), "r"(a[3]), "r"(b[0]), "r"(b[1]));
}

__device__ __forceinline__ void ldm4(unsigned& r0, unsigned& r1, unsigned& r2, unsigned& r3,
                                     const void* p) {
    unsigned a = (unsigned)__cvta_generic_to_shared(p);
    asm volatile("ldmatrix.sync.aligned.m8n8.x4.shared.b16 {%0,%1,%2,%3},[%4];"
                 : "=r"(r0), "=r"(r1), "=r"(r2), "=r"(r3) : "r"(a));
}
__device__ __forceinline__ void ldm4t(unsigned& r0, unsigned& r1, unsigned& r2, unsigned& r3,
                                      const void* p) {
    unsigned a = (unsigned)__cvta_generic_to_shared(p);
    asm volatile("ldmatrix.sync.aligned.m8n8.x4.trans.shared.b16 {%0,%1,%2,%3},[%4];"
                 : "=r"(r0), "=r"(r1), "=r"(r2), "=r"(r3) : "r"(a));
}

__device__ __forceinline__ uint4 cvt8(float4 a, float4 b) {
    uint4 u;
    u.x = pk2(a.x, a.y); u.y = pk2(a.z, a.w);
    u.z = pk2(b.x, b.y); u.w = pk2(b.z, b.w);
    return u;
}

// ---------------------------------------------------------------------------
// GEMM: out[M,1536] = A[M,1536] @ W[1536,1536] + bias. fp16 mma m16n8k16.
// BM=BN=128, BK=32, 256 threads (8 warps 2x4), warp tile 64x32.
// As[128][40] halfs (row-major [m][k]); Bs[32][136] halfs ([k][n]).
// ---------------------------------------------------------------------------
#define GASTR 40
#define GBSTR 136
__global__ __launch_bounds__(256) void gemm_f16(
    const float* __restrict__ A, const float* __restrict__ W,
    const float* __restrict__ bias, float* __restrict__ out, int M)
{
    __shared__ __half As[128 * GASTR];
    __shared__ __half Bs[32 * GBSTR];
    const int bm = blockIdx.x * 128, bn = blockIdx.y * 128;
    const int tid = threadIdx.x, lane = tid & 31, warp = tid >> 5;
    const int wm = (warp >> 2) * 64, wn = (warp & 3) * 32;
    const int gi = lane >> 2, ti = lane & 3;

    float acc[4][4][4];
#pragma unroll
    for (int i = 0; i < 4; i++)
#pragma unroll
        for (int j = 0; j < 4; j++)
#pragma unroll
            for (int c = 0; c < 4; c++) acc[i][j][c] = 0.f;

    // staging indices
    const int ar = tid >> 1, ac = (tid & 1) * 16;   // A: row 0..127, col grp
    const int br = tid >> 3, bc = (tid & 7) * 16;   // B: row 0..31,  col grp

    float4 ra[4], rb[4];
    {
        const float* ap = A + (size_t)(bm + ar) * DIMF + ac;
        bool ok = bm + ar < M;
#pragma unroll
        for (int u = 0; u < 4; u++)
            ra[u] = ok ? *(const float4*)(ap + 4 * u) : make_float4(0, 0, 0, 0);
        const float* bp = W + (size_t)br * DIMF + bn + bc;
#pragma unroll
        for (int u = 0; u < 4; u++) rb[u] = *(const float4*)(bp + 4 * u);
    }

    for (int k0 = 0; k0 < DIMF; k0 += 32) {
        *(uint4*)&As[ar * GASTR + ac]     = cvt8(ra[0], ra[1]);
        *(uint4*)&As[ar * GASTR + ac + 8] = cvt8(ra[2], ra[3]);
        *(uint4*)&Bs[br * GBSTR + bc]     = cvt8(rb[0], rb[1]);
        *(uint4*)&Bs[br * GBSTR + bc + 8] = cvt8(rb[2], rb[3]);
        __syncthreads();

        if (k0 + 32 < DIMF) {
            const float* ap = A + (size_t)(bm + ar) * DIMF + k0 + 32 + ac;
            bool ok = bm + ar < M;
#pragma unroll
            for (int u = 0; u < 4; u++)
                ra[u] = ok ? *(const float4*)(ap + 4 * u) : make_float4(0, 0, 0, 0);
            const float* bp = W + (size_t)(k0 + 32 + br) * DIMF + bn + bc;
#pragma unroll
            for (int u = 0; u < 4; u++) rb[u] = *(const float4*)(bp + 4 * u);
        }

#pragma unroll
        for (int ks = 0; ks < 2; ks++) {
            const int kk = ks * 16;
            unsigned a[4][4], b[2][4];
#pragma unroll
            for (int mt = 0; mt < 4; mt++)
                ldm4(a[mt][0], a[mt][1], a[mt][2], a[mt][3],
                     &As[(wm + 16 * mt + (lane & 15)) * GASTR + kk + 8 * (lane >> 4)]);
#pragma unroll
            for (int ntp = 0; ntp < 2; ntp++)
                ldm4t(b[ntp][0], b[ntp][1], b[ntp][2], b[ntp][3],
                      &Bs[(kk + (lane & 7) + 8 * ((lane >> 3) & 1)) * GBSTR
                          + wn + 16 * ntp + 8 * (lane >> 4)]);
#pragma unroll
            for (int mt = 0; mt < 4; mt++)
#pragma unroll
                for (int ntp = 0; ntp < 2; ntp++) {
                    mma16(acc[mt][2 * ntp],     a[mt], &b[ntp][0]);
                    mma16(acc[mt][2 * ntp + 1], a[mt], &b[ntp][2]);
                }
        }
        __syncthreads();
    }

    // epilogue + bias
#pragma unroll
    for (int mt = 0; mt < 4; mt++) {
#pragma unroll
        for (int nt = 0; nt < 4; nt++) {
            int gr0 = bm + wm + 16 * mt + gi;
            int col = bn + wn + 8 * nt + 2 * ti;
            float2 bv = *(const float2*)&bias[col];
            if (gr0 < M) {
                float2 r = { acc[mt][nt][0] + bv.x, acc[mt][nt][1] + bv.y };
                *(float2*)(out + (size_t)gr0 * DIMF + col) = r;
            }
            if (gr0 + 8 < M) {
                float2 r = { acc[mt][nt][2] + bv.x, acc[mt][nt][3] + bv.y };
                *(float2*)(out + (size_t)(gr0 + 8) * DIMF + col) = r;
            }
        }
    }
}

// ---------------------------------------------------------------------------
// RMSNorm + RoPE (unchanged, 11us)
// ---------------------------------------------------------------------------
__global__ __launch_bounds__(256) void rmsrope(
    float* __restrict__ qbuf, float* __restrict__ kbuf,
    const float* __restrict__ gq, const float* __restrict__ gk,
    const float* __restrict__ fre, const float* __restrict__ fim)
{
    const int t = blockIdx.x;
    float* row = (blockIdx.y == 0 ? qbuf : kbuf) + (size_t)t * DIMF;
    const float* g = blockIdx.y == 0 ? gq : gk;
    const int tid = threadIdx.x;

    float ss = 0.f;
#pragma unroll
    for (int u = 0; u < 6; u++) { float v = row[tid + u * 256]; ss += v * v; }
#pragma unroll
    for (int off = 16; off; off >>= 1) ss += __shfl_xor_sync(0xffffffffu, ss, off);
    __shared__ float red[8];
    if ((tid & 31) == 0) red[tid >> 5] = ss;
    __syncthreads();
    float tot = red[0] + red[1] + red[2] + red[3] + red[4] + red[5] + red[6] + red[7];
    float r = rsqrtf(tot * (1.f / 1536.f) + 1e-6f);

    const int wi = t % 52;
    const int hi = t / 52;
#pragma unroll
    for (int u = 0; u < 3; u++) {
        int p = tid + u * 256;
        int hh = p >> 6, c = p & 63;
        int d0 = hh * 128 + 2 * c;
        int frow = (c < 22) ? 3 : (c < 43) ? hi : wi;
        float cr = fre[frow * 64 + c], ci = fim[frow * 64 + c];
        float v0 = row[d0] * r * g[d0];
        float v1 = row[d0 + 1] * r * g[d0 + 1];
        row[d0]     = v0 * cr - v1 * ci;
        row[d0 + 1] = v0 * ci + v1 * cr;
    }
}

// ---------------------------------------------------------------------------
// Flash attention, fp16 mma m16n8k16. Block = (64 q, head), 128 threads,
// 4 warps x 16 rows. Q frags in regs; K,V staged row-major [kv][d] as half
// (stride 136). QK B-frags: ldmatrix; PV B-frags: ldmatrix.trans (free
// transpose); P stays in registers (S-frag layout == A-frag layout).
// smem: 2 * 64*136*2 = 34816 B -> 2+ blocks/SM.
// ---------------------------------------------------------------------------
#define KVSTR 136
__global__ __launch_bounds__(128, 2) void attn_f16(
    const float* __restrict__ q, const float* __restrict__ knew,
    const float* __restrict__ vnew, const float* __restrict__ ck,
    const float* __restrict__ cv, float* __restrict__ out)
{
    extern __shared__ __half sm[];
    __half* Ks = sm;                 // [kv 64][d 136]
    __half* Vs = sm + 64 * KVSTR;    // [kv 64][d 136]

    const int h = blockIdx.y, q0 = blockIdx.x * 64;
    const int tid = threadIdx.x, lane = tid & 31, warp = tid >> 5;
    const int gi = lane >> 2, ti = lane & 3;

    // Q fragments: warp rows q0+16w+gi / +8; 8 k16-tiles x 4 half2 regs
    unsigned qf[8][4];
    {
        const float sc = 0.08838834764831845f; // 1/sqrt(128)
        int r0 = q0 + warp * 16 + gi, r1 = r0 + 8;
        const float* p0 = q + (size_t)r0 * DIMF + h * HD;
        const float* p1 = q + (size_t)r1 * DIMF + h * HD;
        bool k0ok = r0 < SEQ, k1ok = r1 < SEQ;
#pragma unroll
        for (int kt = 0; kt < 8; kt++) {
            int c = 16 * kt + 2 * ti;
            float2 u0 = k0ok ? *(const float2*)(p0 + c)     : make_float2(0, 0);
            float2 u2 = k0ok ? *(const float2*)(p0 + c + 8) : make_float2(0, 0);
            float2 u1 = k1ok ? *(const float2*)(p1 + c)     : make_float2(0, 0);
            float2 u3 = k1ok ? *(const float2*)(p1 + c + 8) : make_float2(0, 0);
            qf[kt][0] = pk2(u0.x * sc, u0.y * sc);
            qf[kt][1] = pk2(u1.x * sc, u1.y * sc);
            qf[kt][2] = pk2(u2.x * sc, u2.y * sc);
            qf[kt][3] = pk2(u3.x * sc, u3.y * sc);
        }
    }

    float m0v = -1e30f, m1v = -1e30f, l0 = 0.f, l1 = 0.f;
    float o[16][4];
#pragma unroll
    for (int i = 0; i < 16; i++)
#pragma unroll
        for (int c = 0; c < 4; c++) o[i][c] = 0.f;

    // staging: 2 threads per kv row, 64 d each
    const int sr = tid >> 1, sd = (tid & 1) * 64;

    for (int kv0 = 0; kv0 < LKV; kv0 += 64) {
        {
            int j = kv0 + sr;
            bool ok = j < LKV;
            const float* ksrc; const float* vsrc;
            if (j < 1560)      { ksrc = ck + ((size_t)j * NH + h) * HD;
                                 vsrc = cv + ((size_t)j * NH + h) * HD; }
            else if (j < 3120) { ksrc = ck + ((size_t)(j + 1560) * NH + h) * HD;
                                 vsrc = cv + ((size_t)(j + 1560) * NH + h) * HD; }
            else               { ksrc = knew + (size_t)(j - 3120) * DIMF + h * HD;
                                 vsrc = vnew + (size_t)(j - 3120) * DIMF + h * HD; }
#pragma unroll
            for (int u = 0; u < 8; u++) {
                int d = sd + u * 8;
                float4 a = ok ? *(const float4*)(ksrc + d)     : make_float4(0, 0, 0, 0);
                float4 b = ok ? *(const float4*)(ksrc + d + 4) : make_float4(0, 0, 0, 0);
                *(uint4*)&Ks[sr * KVSTR + d] = cvt8(a, b);
                float4 c = ok ? *(const float4*)(vsrc + d)     : make_float4(0, 0, 0, 0);
                float4 e = ok ? *(const float4*)(vsrc + d + 4) : make_float4(0, 0, 0, 0);
                *(uint4*)&Vs[sr * KVSTR + d] = cvt8(c, e);
            }
        }
        __syncthreads();

        // --- S = Q K^T : warp computes 16 x 64 ---
        float s[8][4];
#pragma unroll
        for (int nt = 0; nt < 8; nt++)
#pragma unroll
            for (int c = 0; c < 4; c++) s[nt][c] = 0.f;
#pragma unroll
        for (int kt = 0; kt < 8; kt++) {
            const int kk = 16 * kt;
#pragma unroll
            for (int ntp = 0; ntp < 4; ntp++) {
                unsigned b[4];
                ldm4(b[0], b[1], b[2], b[3],
                     &Ks[(16 * ntp + (lane & 7) + 8 * ((lane >> 4) & 1)) * KVSTR
                         + kk + 8 * ((lane >> 3) & 1)]);
                mma16(s[2 * ntp],     qf[kt], &b[0]);
                mma16(s[2 * ntp + 1], qf[kt], &b[2]);
            }
        }

        // tail mask
        if (kv0 + 64 > LKV) {
#pragma unroll
            for (int nt = 0; nt < 8; nt++) {
                int col = kv0 + 8 * nt + 2 * ti;
                if (col >= LKV)     { s[nt][0] = -1e30f; s[nt][2] = -1e30f; }
                if (col + 1 >= LKV) { s[nt][1] = -1e30f; s[nt][3] = -1e30f; }
            }
        }

        // --- online softmax; produce P fragments in registers ---
        unsigned pf[4][4];
        {
            float mx = -1e30f;
#pragma unroll
            for (int nt = 0; nt < 8; nt++) mx = fmaxf(mx, fmaxf(s[nt][0], s[nt][1]));
            mx = fmaxf(mx, __shfl_xor_sync(0xffffffffu, mx, 1));
            mx = fmaxf(mx, __shfl_xor_sync(0xffffffffu, mx, 2));
            float mn = fmaxf(m0v, mx);
            float al = __expf(m0v - mn);
            float rs = 0.f;
#pragma unroll
            for (int nt = 0; nt < 8; nt++) {
                float p0 = __expf(s[nt][0] - mn), p1 = __expf(s[nt][1] - mn);
                rs += p0 + p1;
                s[nt][0] = p0; s[nt][1] = p1;
            }
            rs += __shfl_xor_sync(0xffffffffu, rs, 1);
            rs += __shfl_xor_sync(0xffffffffu, rs, 2);
            l0 = l0 * al + rs; m0v = mn;
#pragma unroll
            for (int nt = 0; nt < 16; nt++) { o[nt][0] *= al; o[nt][1] *= al; }
        }
        {
            float mx = -1e30f;
#pragma unroll
            for (int nt = 0; nt < 8; nt++) mx = fmaxf(mx, fmaxf(s[nt][2], s[nt][3]));
            mx = fmaxf(mx, __shfl_xor_sync(0xffffffffu, mx, 1));
            mx = fmaxf(mx, __shfl_xor_sync(0xffffffffu, mx, 2));
            float mn = fmaxf(m1v, mx);
            float al = __expf(m1v - mn);
            float rs = 0.f;
#pragma unroll
            for (int nt = 0; nt < 8; nt++) {
                float p2 = __expf(s[nt][2] - mn), p3 = __expf(s[nt][3] - mn);
                rs += p2 + p3;
                s[nt][2] = p2; s[nt][3] = p3;
            }
            rs += __shfl_xor_sync(0xffffffffu, rs, 1);
            rs += __shfl_xor_sync(0xffffffffu, rs, 2);
            l1 = l1 * al + rs; m1v = mn;
#pragma unroll
            for (int nt = 0; nt < 16; nt++) { o[nt][2] *= al; o[nt][3] *= al; }
        }
        // S-frag -> A-frag: pf[j] covers kv 16j..16j+15
#pragma unroll
        for (int j = 0; j < 4; j++) {
            pf[j][0] = pk2(s[2 * j][0],     s[2 * j][1]);
            pf[j][1] = pk2(s[2 * j][2],     s[2 * j][3]);
            pf[j][2] = pk2(s[2 * j + 1][0], s[2 * j + 1][1]);
            pf[j][3] = pk2(s[2 * j + 1][2], s[2 * j + 1][3]);
        }

        // --- O += P V ---
#pragma unroll
        for (int j = 0; j < 4; j++) {
#pragma unroll
            for (int ntp = 0; ntp < 8; ntp++) {
                unsigned b[4];
                ldm4t(b[0], b[1], b[2], b[3],
                      &Vs[(16 * j + (lane & 7) + 8 * ((lane >> 3) & 1)) * KVSTR
                          + 16 * ntp + 8 * ((lane >> 4) & 1)]);
                mma16(o[2 * ntp],     pf[j], &b[0]);
                mma16(o[2 * ntp + 1], pf[j], &b[2]);
            }
        }
        __syncthreads();
    }

    // epilogue
    {
        int r0 = q0 + warp * 16 + gi, r1 = r0 + 8;
        float i0 = 1.f / l0, i1 = 1.f / l1;
#pragma unroll
        for (int nt = 0; nt < 16; nt++) {
            int c = h * HD + 8 * nt + 2 * ti;
            if (r0 < SEQ) {
                float2 v = { o[nt][0] * i0, o[nt][1] * i0 };
                *(float2*)(out + (size_t)r0 * DIMF + c) = v;
            }
            if (r1 < SEQ) {
                float2 v = { o[nt][2] * i1, o[nt][3] * i1 };
                *(float2*)(out + (size_t)r1 * DIMF + c) = v;
            }
        }
    }
}

// ---------------------------------------------------------------------------
extern "C" void kernel_launch(void* const* d_in, const int* in_sizes, int n_in,
                              void* d_out, int out_size)
{
    (void)in_sizes; (void)n_in; (void)out_size;
    const float* x   = (const float*)d_in[0];
    const float* ck  = (const float*)d_in[1];
    const float* cv  = (const float*)d_in[2];
    const float* fre = (const float*)d_in[3];
    const float* fim = (const float*)d_in[4];
    const float* wq  = (const float*)d_in[5];
    const float* bq  = (const float*)d_in[6];
    const float* wk  = (const float*)d_in[7];
    const float* bk  = (const float*)d_in[8];
    const float* wv  = (const float*)d_in[9];
    const float* bv  = (const float*)d_in[10];
    const float* wo  = (const float*)d_in[11];
    const float* bo  = (const float*)d_in[12];
    const float* gq  = (const float*)d_in[13];
    const float* gk  = (const float*)d_in[14];
    float* out = (float*)d_out;

    float *q, *k, *v, *o;
    cudaGetSymbolAddress((void**)&q, g_q);
    cudaGetSymbolAddress((void**)&k, g_k);
    cudaGetSymbolAddress((void**)&v, g_v);
    cudaGetSymbolAddress((void**)&o, g_o);

    const int attn_smem = 2 * 64 * KVSTR * (int)sizeof(__half); // 34816
    cudaFuncSetAttribute(attn_f16, cudaFuncAttributeMaxDynamicSharedMemorySize, attn_smem);

    dim3 gg(13, 12);
    gemm_f16<<<gg, 256>>>(x, wq, bq, q, SEQ);
    gemm_f16<<<gg, 256>>>(x, wk, bk, k, SEQ);
    gemm_f16<<<gg, 256>>>(x, wv, bv, v, SEQ);
    rmsrope<<<dim3(SEQ, 2), 256>>>(q, k, gq, gk, fre, fim);
    attn_f16<<<dim3(25, NH), 128, attn_smem>>>(q, k, v, ck, cv, o);
    gemm_f16<<<gg, 256>>>(o, wo, bo, out, SEQ);
}